// round 7
// baseline (speedup 1.0000x reference)
#include <cuda_runtime.h>
#include <cuda_fp16.h>
#include <cstdint>

typedef unsigned long long u64;
typedef unsigned int u32;
typedef unsigned short u16;

#define A_NODES 256
#define F_DIM   256
#define C_DIM   32

// ---------------- scratch (device globals; no runtime allocation) ------------
__device__ float g_right[A_NODES * C_DIM];                    // [b][d]
__device__ __half g_Ah[A_NODES * C_DIM];                      // [a][kpos(c)] fp16
__device__ __half g_Bh[(size_t)A_NODES * C_DIM * F_DIM];      // [b][c][f] fp16, 4 MB

// permuted position of k within a 16-col block: (2t,2t+1,2t+8,2t+9) adjacent
__device__ __host__ __forceinline__ int kpos(int k) {
    return (k & 1) | (((k >> 3) & 1) << 1) | (((k >> 1) & 3) << 2);
}

// ---------------- f32x2 helpers ----------------------------------------------
__device__ __forceinline__ u64 pack2(float x, float y) {
    u64 r; asm("mov.b64 %0, {%1, %2};" : "=l"(r) : "f"(x), "f"(y)); return r;
}
__device__ __forceinline__ void fma2(u64& d, u64 a, u64 b) {
    asm("fma.rn.f32x2 %0, %1, %2, %0;" : "+l"(d) : "l"(a), "l"(b));
}
__device__ __forceinline__ float2 unpack2(u64 v) {
    float2 f; asm("mov.b64 {%0, %1}, %2;" : "=f"(f.x), "=f"(f.y) : "l"(v)); return f;
}

// ---------------- mma.sync fp16 ------------------------------------------------
__device__ __forceinline__ void mma_f16(float* d, const u32* a, const u32* b) {
    asm volatile("mma.sync.aligned.m16n8k16.row.col.f32.f16.f16.f32 "
        "{%0,%1,%2,%3}, {%4,%5,%6,%7}, {%8,%9}, {%0,%1,%2,%3};"
        : "+f"(d[0]), "+f"(d[1]), "+f"(d[2]), "+f"(d[3])
        : "r"(a[0]), "r"(a[1]), "r"(a[2]), "r"(a[3]), "r"(b[0]), "r"(b[1]));
}

// ---------------- Kernel A: LayerNorm + dual projections (warp-per-node) ------
// grid 128 x 64 threads = 256 warps, one node per warp, no __syncthreads.
__global__ void __launch_bounds__(64) k_lnproj(
        const float* __restrict__ nv, const float* __restrict__ mask,
        const float* __restrict__ lns, const float* __restrict__ lnb,
        const float* __restrict__ Wl, const float* __restrict__ bl,
        const float* __restrict__ Wr, const float* __restrict__ br) {
    int a = blockIdx.x * 2 + (threadIdx.x >> 5);
    int lane = threadIdx.x & 31;

    const float* row = nv + (size_t)a * F_DIM;
    float4 v0 = *(const float4*)(row + lane * 4);
    float4 v1 = *(const float4*)(row + 128 + lane * 4);
    float x[8] = {v0.x, v0.y, v0.z, v0.w, v1.x, v1.y, v1.z, v1.w};

    float s = 0.f, s2 = 0.f;
    #pragma unroll
    for (int j = 0; j < 8; j++) { s += x[j]; s2 = fmaf(x[j], x[j], s2); }
    #pragma unroll
    for (int o = 16; o; o >>= 1) {
        s  += __shfl_xor_sync(0xffffffffu, s,  o);
        s2 += __shfl_xor_sync(0xffffffffu, s2, o);
    }
    float mu = s * (1.0f / F_DIM);
    float var = s2 * (1.0f / F_DIM) - mu * mu;
    float rs = rsqrtf(var + 1e-5f);

    float4 sc0 = *(const float4*)(lns + lane * 4);
    float4 sc1 = *(const float4*)(lns + 128 + lane * 4);
    float4 bb0 = *(const float4*)(lnb + lane * 4);
    float4 bb1 = *(const float4*)(lnb + 128 + lane * 4);
    float scv[8] = {sc0.x, sc0.y, sc0.z, sc0.w, sc1.x, sc1.y, sc1.z, sc1.w};
    float bbv[8] = {bb0.x, bb0.y, bb0.z, bb0.w, bb1.x, bb1.y, bb1.z, bb1.w};

    float act[8];
    #pragma unroll
    for (int j = 0; j < 8; j++)
        act[j] = fmaf((x[j] - mu) * rs, scv[j], bbv[j]);

    float pl0 = 0.f, pl1 = 0.f, pr0 = 0.f, pr1 = 0.f;
    #pragma unroll 8
    for (int f4 = 0; f4 < 32; f4++) {
        float a0 = __shfl_sync(0xffffffffu, act[0], f4);
        float a1 = __shfl_sync(0xffffffffu, act[1], f4);
        float a2 = __shfl_sync(0xffffffffu, act[2], f4);
        float a3 = __shfl_sync(0xffffffffu, act[3], f4);
        int fb = f4 * 4;
        pl0 = fmaf(a0, Wl[(fb + 0) * 32 + lane], pl0);
        pl1 = fmaf(a1, Wl[(fb + 1) * 32 + lane], pl1);
        pl0 = fmaf(a2, Wl[(fb + 2) * 32 + lane], pl0);
        pl1 = fmaf(a3, Wl[(fb + 3) * 32 + lane], pl1);
        pr0 = fmaf(a0, Wr[(fb + 0) * 32 + lane], pr0);
        pr1 = fmaf(a1, Wr[(fb + 1) * 32 + lane], pr1);
        pr0 = fmaf(a2, Wr[(fb + 2) * 32 + lane], pr0);
        pr1 = fmaf(a3, Wr[(fb + 3) * 32 + lane], pr1);
    }
    #pragma unroll 8
    for (int f4 = 0; f4 < 32; f4++) {
        float a0 = __shfl_sync(0xffffffffu, act[4], f4);
        float a1 = __shfl_sync(0xffffffffu, act[5], f4);
        float a2 = __shfl_sync(0xffffffffu, act[6], f4);
        float a3 = __shfl_sync(0xffffffffu, act[7], f4);
        int fb = 128 + f4 * 4;
        pl0 = fmaf(a0, Wl[(fb + 0) * 32 + lane], pl0);
        pl1 = fmaf(a1, Wl[(fb + 1) * 32 + lane], pl1);
        pl0 = fmaf(a2, Wl[(fb + 2) * 32 + lane], pl0);
        pl1 = fmaf(a3, Wl[(fb + 3) * 32 + lane], pl1);
        pr0 = fmaf(a0, Wr[(fb + 0) * 32 + lane], pr0);
        pr1 = fmaf(a1, Wr[(fb + 1) * 32 + lane], pr1);
        pr0 = fmaf(a2, Wr[(fb + 2) * 32 + lane], pr0);
        pr1 = fmaf(a3, Wr[(fb + 3) * 32 + lane], pr1);
    }

    float m = mask[a];
    g_right[a * C_DIM + lane] = (pr0 + pr1 + br[lane]) * m;
    int pos = (lane >> 4) * 16 + kpos(lane & 15);
    g_Ah[a * C_DIM + pos] = __float2half_rn((pl0 + pl1 + bl[lane]) * m);
}

// ---------------- Kernel B: T[b,c,f] = sum_d right[b,d]*Wo[c*32+d,f] -> fp16 --
__global__ void __launch_bounds__(256, 2) k_makeT(const float* __restrict__ Wo) {
    int c  = blockIdx.x;
    int b0 = blockIdx.y * 32;
    int f  = threadIdx.x;

    __shared__ __align__(16) float rT[32 * 32];

    u64 w2[32];
    #pragma unroll
    for (int d = 0; d < 32; d++) {
        float wv = Wo[(size_t)(c * 32 + d) * F_DIM + f];
        w2[d] = pack2(wv, wv);
    }
    for (int i = f; i < 1024; i += 256) {
        int d = i >> 5, bl_ = i & 31;
        rT[d * 32 + bl_] = g_right[(b0 + bl_) * C_DIM + d];
    }
    __syncthreads();

    #pragma unroll
    for (int bq = 0; bq < 32; bq += 4) {
        u64 a0 = 0ULL, a1 = 0ULL;
        #pragma unroll
        for (int d = 0; d < 32; d++) {
            ulonglong2 r2 = *(const ulonglong2*)&rT[d * 32 + bq];
            fma2(a0, r2.x, w2[d]);
            fma2(a1, r2.y, w2[d]);
        }
        float2 v0 = unpack2(a0), v1 = unpack2(a1);
        __half* p = g_Bh + ((size_t)(b0 + bq) * C_DIM + c) * F_DIM + f;
        p[0]                     = __float2half_rn(v0.x);
        p[1 * C_DIM * F_DIM]     = __float2half_rn(v0.y);
        p[2 * C_DIM * F_DIM]     = __float2half_rn(v1.x);
        p[3 * C_DIM * F_DIM]     = __float2half_rn(v1.y);
    }
}

// ---------------- Kernel C: fp16 single-pass mma.sync GEMM --------------------
// Grid (256 b, 2 mt, 4 nt) = 2048 CTAs. Tile M=128 x N=64, 8 warps, warp 32x32,
// K=32 (2 kblocks), 16 MMA per warp. acc=32 regs -> occ 3.
#define LDA 48
#define LDB 52

__global__ void __launch_bounds__(256, 3) k_gemm(const float* __restrict__ bo,
                                                 float* __restrict__ out) {
    __shared__ __align__(16) u16 A_s[128 * LDA];
    __shared__ __align__(16) u16 B_s[64 * LDB];
    __shared__ float bo_s[64];

    int b  = blockIdx.x;
    int mt = blockIdx.y;
    int nt = blockIdx.z;
    int t = threadIdx.x, w = t >> 5, lane = t & 31;
    int g = lane >> 2, tig = lane & 3;
    int wm = w & 3, wn = w >> 2;
    int m0 = wm * 32, n0 = wn * 32;

    // --- A tile: 128 x 32 fp16 (kpos-permuted in g_Ah) ---
    #pragma unroll
    for (int i = 0; i < 2; i++) {
        int id = t + 256 * i;
        int m = id >> 2, q = id & 3;
        uint4 v = *(const uint4*)(g_Ah + ((size_t)mt * 128 + m) * 32 + q * 8);
        *(uint4*)(&A_s[m * LDA + q * 8]) = v;
    }

    // --- B tile: g_Bh[b][c][nt*64+f] -> B_s[f][kpos(c)] ---
    {
        int f = t & 63, cq = t >> 6;
        const __half* src = g_Bh + (size_t)b * (C_DIM * F_DIM) + nt * 64 + f;
        #pragma unroll
        for (int j = 0; j < 8; j++) {
            int c = cq * 8 + j;
            u16 v = __half_as_ushort(src[c * F_DIM]);
            int pos = (c >> 4) * 16 + kpos(c & 15);
            B_s[f * LDB + pos] = v;
        }
    }
    if (t < 64) bo_s[t] = bo[nt * 64 + t];
    __syncthreads();

    float acc[2][4][4];
    #pragma unroll
    for (int mi = 0; mi < 2; mi++)
        #pragma unroll
        for (int ni = 0; ni < 4; ni++)
            #pragma unroll
            for (int q = 0; q < 4; q++) acc[mi][ni][q] = 0.f;

    #pragma unroll
    for (int kb = 0; kb < 2; kb++) {
        int col = kb * 16 + tig * 4;

        u32 af[2][4], bfr[4][2];
        #pragma unroll
        for (int mi = 0; mi < 2; mi++) {
            int row = m0 + mi * 16 + g;
            uint2 v0 = *(const uint2*)&A_s[row * LDA + col];
            uint2 v1 = *(const uint2*)&A_s[(row + 8) * LDA + col];
            af[mi][0] = v0.x; af[mi][2] = v0.y;
            af[mi][1] = v1.x; af[mi][3] = v1.y;
        }
        #pragma unroll
        for (int ni = 0; ni < 4; ni++) {
            uint2 v = *(const uint2*)&B_s[(n0 + ni * 8 + g) * LDB + col];
            bfr[ni][0] = v.x; bfr[ni][1] = v.y;
        }
        #pragma unroll
        for (int mi = 0; mi < 2; mi++)
            #pragma unroll
            for (int ni = 0; ni < 4; ni++)
                mma_f16(acc[mi][ni], af[mi], bfr[ni]);
    }

    // --- epilogue: out[a][b][f] + bo[f] ---
    #pragma unroll
    for (int mi = 0; mi < 2; mi++) {
        size_t a_row = (size_t)mt * 128 + m0 + mi * 16 + g;
        float* prow = out + a_row * ((size_t)A_NODES * F_DIM) + (size_t)b * F_DIM + nt * 64;
        #pragma unroll
        for (int ni = 0; ni < 4; ni++) {
            int fl = n0 + ni * 8 + tig * 2;
            float bx = bo_s[fl], by = bo_s[fl + 1];
            float2 v0 = make_float2(acc[mi][ni][0] + bx, acc[mi][ni][1] + by);
            float2 v1 = make_float2(acc[mi][ni][2] + bx, acc[mi][ni][3] + by);
            *(float2*)(prow + fl) = v0;
            *(float2*)(prow + 8 * ((size_t)A_NODES * F_DIM) + fl) = v1;
        }
    }
}

// ---------------- launch ------------------------------------------------------
extern "C" void kernel_launch(void* const* d_in, const int* in_sizes, int n_in,
                              void* d_out, int out_size) {
    const float* nv   = (const float*)d_in[0];
    const float* mask = (const float*)d_in[1];
    const float* lns  = (const float*)d_in[2];
    const float* lnb  = (const float*)d_in[3];
    const float* Wl   = (const float*)d_in[4];
    const float* bl   = (const float*)d_in[5];
    const float* Wr   = (const float*)d_in[6];
    const float* br   = (const float*)d_in[7];
    const float* Wo   = (const float*)d_in[8];
    const float* bo   = (const float*)d_in[9];
    float* out = (float*)d_out;

    k_lnproj<<<128, 64>>>(nv, mask, lns, lnb, Wl, bl, Wr, br);
    k_makeT<<<dim3(32, 8), 256>>>(Wo);
    k_gemm<<<dim3(256, 2, 4), 256>>>(bo, out);
}

// round 8
// speedup vs baseline: 1.6413x; 1.6413x over previous
#include <cuda_runtime.h>
#include <cuda_fp16.h>
#include <cstdint>

typedef unsigned long long u64;
typedef unsigned int u32;
typedef unsigned short u16;

#define A_NODES 256
#define F_DIM   256
#define C_DIM   32

// ---------------- scratch (device globals; no runtime allocation) ------------
__device__ float g_right[A_NODES * C_DIM];                    // [b][d]
__device__ __half g_Ah[A_NODES * C_DIM];                      // [a][kpos(c)] fp16
__device__ __half g_Bh[(size_t)A_NODES * C_DIM * F_DIM];      // [b][c][f] fp16, 4 MB

// permuted position of k within a 16-col block: (2t,2t+1,2t+8,2t+9) adjacent
__device__ __host__ __forceinline__ int kpos(int k) {
    return (k & 1) | (((k >> 3) & 1) << 1) | (((k >> 1) & 3) << 2);
}

// ---------------- f32x2 helpers ----------------------------------------------
__device__ __forceinline__ u64 pack2(float x, float y) {
    u64 r; asm("mov.b64 %0, {%1, %2};" : "=l"(r) : "f"(x), "f"(y)); return r;
}
__device__ __forceinline__ void fma2(u64& d, u64 a, u64 b) {
    asm("fma.rn.f32x2 %0, %1, %2, %0;" : "+l"(d) : "l"(a), "l"(b));
}
__device__ __forceinline__ float2 unpack2(u64 v) {
    float2 f; asm("mov.b64 {%0, %1}, %2;" : "=f"(f.x), "=f"(f.y) : "l"(v)); return f;
}

// ---------------- mma.sync fp16 ------------------------------------------------
__device__ __forceinline__ void mma_f16(float* d, const u32* a, const u32* b) {
    asm volatile("mma.sync.aligned.m16n8k16.row.col.f32.f16.f16.f32 "
        "{%0,%1,%2,%3}, {%4,%5,%6,%7}, {%8,%9}, {%0,%1,%2,%3};"
        : "+f"(d[0]), "+f"(d[1]), "+f"(d[2]), "+f"(d[3])
        : "r"(a[0]), "r"(a[1]), "r"(a[2]), "r"(a[3]), "r"(b[0]), "r"(b[1]));
}

// ---------------- Kernel A: LayerNorm + dual projections ----------------------
// (R6 version: block per node, 256 threads — proven config)
__global__ void k_lnproj(const float* __restrict__ nv, const float* __restrict__ mask,
                         const float* __restrict__ lns, const float* __restrict__ lnb,
                         const float* __restrict__ Wl, const float* __restrict__ bl,
                         const float* __restrict__ Wr, const float* __restrict__ br) {
    int a = blockIdx.x, t = threadIdx.x;
    __shared__ float act[F_DIM];
    __shared__ float red[16];
    __shared__ float pls[256], prs[256];
    __shared__ float s_mu, s_rs;

    float x = nv[a * F_DIM + t];
    float s = x, s2 = x * x;
    #pragma unroll
    for (int o = 16; o; o >>= 1) {
        s  += __shfl_xor_sync(0xffffffffu, s,  o);
        s2 += __shfl_xor_sync(0xffffffffu, s2, o);
    }
    if ((t & 31) == 0) { red[t >> 5] = s; red[8 + (t >> 5)] = s2; }
    __syncthreads();
    if (t == 0) {
        float S = 0.f, S2 = 0.f;
        #pragma unroll
        for (int i = 0; i < 8; i++) { S += red[i]; S2 += red[8 + i]; }
        float m = S * (1.0f / F_DIM);
        float v = S2 * (1.0f / F_DIM) - m * m;
        s_mu = m;
        s_rs = rsqrtf(v + 1e-5f);
    }
    __syncthreads();
    act[t] = (x - s_mu) * s_rs * lns[t] + lnb[t];
    __syncthreads();

    int c = t & 31, ch = t >> 5;
    float pl = 0.f, pr = 0.f;
    #pragma unroll
    for (int k = 0; k < 32; k++) {
        int f = ch * 32 + k;
        float av = act[f];
        pl = fmaf(av, Wl[f * C_DIM + c], pl);
        pr = fmaf(av, Wr[f * C_DIM + c], pr);
    }
    pls[t] = pl; prs[t] = pr;
    __syncthreads();
    if (t < 32) {
        float L = bl[t], R = br[t];
        #pragma unroll
        for (int k = 0; k < 8; k++) { L += pls[k * 32 + t]; R += prs[k * 32 + t]; }
        float m = mask[a];
        g_right[a * C_DIM + t] = R * m;
        int pos = (t >> 4) * 16 + kpos(t & 15);
        g_Ah[a * 32 + pos] = __float2half_rn(L * m);
    }
}

// ---------------- Kernel B: T[b,c,f] = sum_d right[b,d]*Wo[c*32+d,f] -> fp16 --
__global__ void __launch_bounds__(256, 2) k_makeT(const float* __restrict__ Wo) {
    int c  = blockIdx.x;
    int b0 = blockIdx.y * 32;
    int f  = threadIdx.x;

    __shared__ __align__(16) float rT[32 * 32];

    u64 w2[32];
    #pragma unroll
    for (int d = 0; d < 32; d++) {
        float wv = Wo[(size_t)(c * 32 + d) * F_DIM + f];
        w2[d] = pack2(wv, wv);
    }
    for (int i = f; i < 1024; i += 256) {
        int d = i >> 5, bl_ = i & 31;
        rT[d * 32 + bl_] = g_right[(b0 + bl_) * C_DIM + d];
    }
    __syncthreads();

    #pragma unroll
    for (int bq = 0; bq < 32; bq += 4) {
        u64 a0 = 0ULL, a1 = 0ULL;
        #pragma unroll
        for (int d = 0; d < 32; d++) {
            ulonglong2 r2 = *(const ulonglong2*)&rT[d * 32 + bq];
            fma2(a0, r2.x, w2[d]);
            fma2(a1, r2.y, w2[d]);
        }
        float2 v0 = unpack2(a0), v1 = unpack2(a1);
        __half* p = g_Bh + ((size_t)(b0 + bq) * C_DIM + c) * F_DIM + f;
        p[0]                     = __float2half_rn(v0.x);
        p[1 * C_DIM * F_DIM]     = __float2half_rn(v0.y);
        p[2 * C_DIM * F_DIM]     = __float2half_rn(v1.x);
        p[3 * C_DIM * F_DIM]     = __float2half_rn(v1.y);
    }
}

// ---------------- Kernel C: fp16 single-pass mma.sync GEMM --------------------
// Grid (256 b, 2 mt, 4 nt) = 2048 CTAs. Tile M=128 x N=64, 8 warps, warp 32x32,
// K=32 (2 kblocks), 16 MMA per warp. acc=32 regs -> occ 3.
#define LDA 48
#define LDB 52

__global__ void __launch_bounds__(256, 3) k_gemm(const float* __restrict__ bo,
                                                 float* __restrict__ out) {
    __shared__ __align__(16) u16 A_s[128 * LDA];
    __shared__ __align__(16) u16 B_s[64 * LDB];
    __shared__ float bo_s[64];

    int b  = blockIdx.x;
    int mt = blockIdx.y;
    int nt = blockIdx.z;
    int t = threadIdx.x, w = t >> 5, lane = t & 31;
    int g = lane >> 2, tig = lane & 3;
    int wm = w & 3, wn = w >> 2;
    int m0 = wm * 32, n0 = wn * 32;

    // --- A tile: 128 x 32 fp16 (kpos-permuted in g_Ah) ---
    #pragma unroll
    for (int i = 0; i < 2; i++) {
        int id = t + 256 * i;
        int m = id >> 2, q = id & 3;
        uint4 v = *(const uint4*)(g_Ah + ((size_t)mt * 128 + m) * 32 + q * 8);
        *(uint4*)(&A_s[m * LDA + q * 8]) = v;
    }

    // --- B tile: g_Bh[b][c][nt*64+f] -> B_s[f][kpos(c)], u32 (f-pair) loads ---
    {
        int c = t >> 3, fpb = t & 7;
        int pos = (c >> 4) * 16 + kpos(c & 15);
        const u32* src = (const u32*)(g_Bh + (size_t)b * (C_DIM * F_DIM) + c * F_DIM + nt * 64);
        #pragma unroll
        for (int j = 0; j < 4; j++) {
            int fp = fpb + 8 * j;
            u32 v = src[fp];
            B_s[(2 * fp) * LDB + pos]     = (u16)(v & 0xffffu);
            B_s[(2 * fp + 1) * LDB + pos] = (u16)(v >> 16);
        }
    }
    if (t < 64) bo_s[t] = bo[nt * 64 + t];
    __syncthreads();

    float acc[2][4][4];
    #pragma unroll
    for (int mi = 0; mi < 2; mi++)
        #pragma unroll
        for (int ni = 0; ni < 4; ni++)
            #pragma unroll
            for (int q = 0; q < 4; q++) acc[mi][ni][q] = 0.f;

    #pragma unroll
    for (int kb = 0; kb < 2; kb++) {
        int col = kb * 16 + tig * 4;

        u32 af[2][4], bfr[4][2];
        #pragma unroll
        for (int mi = 0; mi < 2; mi++) {
            int row = m0 + mi * 16 + g;
            uint2 v0 = *(const uint2*)&A_s[row * LDA + col];
            uint2 v1 = *(const uint2*)&A_s[(row + 8) * LDA + col];
            af[mi][0] = v0.x; af[mi][2] = v0.y;
            af[mi][1] = v1.x; af[mi][3] = v1.y;
        }
        #pragma unroll
        for (int ni = 0; ni < 4; ni++) {
            uint2 v = *(const uint2*)&B_s[(n0 + ni * 8 + g) * LDB + col];
            bfr[ni][0] = v.x; bfr[ni][1] = v.y;
        }
        #pragma unroll
        for (int mi = 0; mi < 2; mi++)
            #pragma unroll
            for (int ni = 0; ni < 4; ni++)
                mma_f16(acc[mi][ni], af[mi], bfr[ni]);
    }

    // --- epilogue: out[a][b][f] + bo[f] ---
    #pragma unroll
    for (int mi = 0; mi < 2; mi++) {
        size_t a_row = (size_t)mt * 128 + m0 + mi * 16 + g;
        float* prow = out + a_row * ((size_t)A_NODES * F_DIM) + (size_t)b * F_DIM + nt * 64;
        #pragma unroll
        for (int ni = 0; ni < 4; ni++) {
            int fl = n0 + ni * 8 + tig * 2;
            float bx = bo_s[fl], by = bo_s[fl + 1];
            float2 v0 = make_float2(acc[mi][ni][0] + bx, acc[mi][ni][1] + by);
            float2 v1 = make_float2(acc[mi][ni][2] + bx, acc[mi][ni][3] + by);
            *(float2*)(prow + fl) = v0;
            *(float2*)(prow + 8 * ((size_t)A_NODES * F_DIM) + fl) = v1;
        }
    }
}

// ---------------- launch ------------------------------------------------------
extern "C" void kernel_launch(void* const* d_in, const int* in_sizes, int n_in,
                              void* d_out, int out_size) {
    const float* nv   = (const float*)d_in[0];
    const float* mask = (const float*)d_in[1];
    const float* lns  = (const float*)d_in[2];
    const float* lnb  = (const float*)d_in[3];
    const float* Wl   = (const float*)d_in[4];
    const float* bl   = (const float*)d_in[5];
    const float* Wr   = (const float*)d_in[6];
    const float* br   = (const float*)d_in[7];
    const float* Wo   = (const float*)d_in[8];
    const float* bo   = (const float*)d_in[9];
    float* out = (float*)d_out;

    k_lnproj<<<A_NODES, 256>>>(nv, mask, lns, lnb, Wl, bl, Wr, br);
    k_makeT<<<dim3(32, 8), 256>>>(Wo);
    k_gemm<<<dim3(256, 2, 4), 256>>>(bo, out);
}

// round 9
// speedup vs baseline: 1.7728x; 1.0801x over previous
#include <cuda_runtime.h>
#include <cuda_fp16.h>
#include <cstdint>

typedef unsigned long long u64;
typedef unsigned int u32;
typedef unsigned short u16;

#define A_NODES 256
#define F_DIM   256
#define C_DIM   32

// ---------------- scratch (device globals; no runtime allocation) ------------
__device__ float g_right[A_NODES * C_DIM];                    // [b][d]
__device__ __half g_Ah[A_NODES * C_DIM];                      // [a][kpos(c)] fp16
__device__ __half g_Bh[(size_t)A_NODES * C_DIM * F_DIM];      // [b][c][f] fp16, 4 MB

// permuted position of k within a 16-col block: (2t,2t+1,2t+8,2t+9) adjacent
__device__ __host__ __forceinline__ int kpos(int k) {
    return (k & 1) | (((k >> 3) & 1) << 1) | (((k >> 1) & 3) << 2);
}

// ---------------- f32x2 helpers ----------------------------------------------
__device__ __forceinline__ u64 pack2(float x, float y) {
    u64 r; asm("mov.b64 %0, {%1, %2};" : "=l"(r) : "f"(x), "f"(y)); return r;
}
__device__ __forceinline__ void fma2(u64& d, u64 a, u64 b) {
    asm("fma.rn.f32x2 %0, %1, %2, %0;" : "+l"(d) : "l"(a), "l"(b));
}
__device__ __forceinline__ float2 unpack2(u64 v) {
    float2 f; asm("mov.b64 {%0, %1}, %2;" : "=f"(f.x), "=f"(f.y) : "l"(v)); return f;
}

// ---------------- mma.sync fp16 ------------------------------------------------
__device__ __forceinline__ void mma_f16(float* d, const u32* a, const u32* b) {
    asm volatile("mma.sync.aligned.m16n8k16.row.col.f32.f16.f16.f32 "
        "{%0,%1,%2,%3}, {%4,%5,%6,%7}, {%8,%9}, {%0,%1,%2,%3};"
        : "+f"(d[0]), "+f"(d[1]), "+f"(d[2]), "+f"(d[3])
        : "r"(a[0]), "r"(a[1]), "r"(a[2]), "r"(a[3]), "r"(b[0]), "r"(b[1]));
}

// ---------------- Kernel A: LayerNorm + dual projections ----------------------
// (block per node, 256 threads — proven config)
__global__ void k_lnproj(const float* __restrict__ nv, const float* __restrict__ mask,
                         const float* __restrict__ lns, const float* __restrict__ lnb,
                         const float* __restrict__ Wl, const float* __restrict__ bl,
                         const float* __restrict__ Wr, const float* __restrict__ br) {
    int a = blockIdx.x, t = threadIdx.x;
    __shared__ float act[F_DIM];
    __shared__ float red[16];
    __shared__ float pls[256], prs[256];
    __shared__ float s_mu, s_rs;

    float x = nv[a * F_DIM + t];
    float s = x, s2 = x * x;
    #pragma unroll
    for (int o = 16; o; o >>= 1) {
        s  += __shfl_xor_sync(0xffffffffu, s,  o);
        s2 += __shfl_xor_sync(0xffffffffu, s2, o);
    }
    if ((t & 31) == 0) { red[t >> 5] = s; red[8 + (t >> 5)] = s2; }
    __syncthreads();
    if (t == 0) {
        float S = 0.f, S2 = 0.f;
        #pragma unroll
        for (int i = 0; i < 8; i++) { S += red[i]; S2 += red[8 + i]; }
        float m = S * (1.0f / F_DIM);
        float v = S2 * (1.0f / F_DIM) - m * m;
        s_mu = m;
        s_rs = rsqrtf(v + 1e-5f);
    }
    __syncthreads();
    act[t] = (x - s_mu) * s_rs * lns[t] + lnb[t];
    __syncthreads();

    int c = t & 31, ch = t >> 5;
    float pl = 0.f, pr = 0.f;
    #pragma unroll
    for (int k = 0; k < 32; k++) {
        int f = ch * 32 + k;
        float av = act[f];
        pl = fmaf(av, Wl[f * C_DIM + c], pl);
        pr = fmaf(av, Wr[f * C_DIM + c], pr);
    }
    pls[t] = pl; prs[t] = pr;
    __syncthreads();
    if (t < 32) {
        float L = bl[t], R = br[t];
        #pragma unroll
        for (int k = 0; k < 8; k++) { L += pls[k * 32 + t]; R += prs[k * 32 + t]; }
        float m = mask[a];
        g_right[a * C_DIM + t] = R * m;
        int pos = (t >> 4) * 16 + kpos(t & 15);
        g_Ah[a * 32 + pos] = __float2half_rn(L * m);
    }
}

// ---------------- Kernel B: T[b,c,f] = sum_d right[b,d]*Wo[c*32+d,f] -> fp16 --
__global__ void __launch_bounds__(256, 2) k_makeT(const float* __restrict__ Wo) {
    int c  = blockIdx.x;
    int b0 = blockIdx.y * 32;
    int f  = threadIdx.x;

    __shared__ __align__(16) float rT[32 * 32];

    u64 w2[32];
    #pragma unroll
    for (int d = 0; d < 32; d++) {
        float wv = Wo[(size_t)(c * 32 + d) * F_DIM + f];
        w2[d] = pack2(wv, wv);
    }
    for (int i = f; i < 1024; i += 256) {
        int d = i >> 5, bl_ = i & 31;
        rT[d * 32 + bl_] = g_right[(b0 + bl_) * C_DIM + d];
    }
    __syncthreads();

    #pragma unroll
    for (int bq = 0; bq < 32; bq += 4) {
        u64 a0 = 0ULL, a1 = 0ULL;
        #pragma unroll
        for (int d = 0; d < 32; d++) {
            ulonglong2 r2 = *(const ulonglong2*)&rT[d * 32 + bq];
            fma2(a0, r2.x, w2[d]);
            fma2(a1, r2.y, w2[d]);
        }
        float2 v0 = unpack2(a0), v1 = unpack2(a1);
        __half* p = g_Bh + ((size_t)(b0 + bq) * C_DIM + c) * F_DIM + f;
        p[0]                     = __float2half_rn(v0.x);
        p[1 * C_DIM * F_DIM]     = __float2half_rn(v0.y);
        p[2 * C_DIM * F_DIM]     = __float2half_rn(v1.x);
        p[3 * C_DIM * F_DIM]     = __float2half_rn(v1.y);
    }
}

// ---------------- Kernel C: fp16 single-pass mma.sync GEMM --------------------
// Grid (256 b, 2 mt, 4 nt) = 2048 CTAs. Tile M=128 x N=64, 8 warps, warp 32x32,
// K=32 (2 kblocks), 16 MMA per warp. acc=32 regs -> occ 3.
// B_s rows n-permuted so epilogue writes are STG.128 over 4 consecutive f.
#define LDA 48
#define LDB 52

__global__ void __launch_bounds__(256, 3) k_gemm(const float* __restrict__ bo,
                                                 float* __restrict__ out) {
    __shared__ __align__(16) u16 A_s[128 * LDA];
    __shared__ __align__(16) u16 B_s[64 * LDB];
    __shared__ __align__(16) float bo_s[64];

    int b  = blockIdx.x;
    int mt = blockIdx.y;
    int nt = blockIdx.z;
    int t = threadIdx.x, w = t >> 5, lane = t & 31;
    int g = lane >> 2, tig = lane & 3;
    int wm = w & 3, wn = w >> 2;
    int m0 = wm * 32, n0 = wn * 32;

    // --- A tile: 128 x 32 fp16 (kpos-permuted in g_Ah) ---
    #pragma unroll
    for (int i = 0; i < 2; i++) {
        int id = t + 256 * i;
        int m = id >> 2, q = id & 3;
        uint4 v = *(const uint4*)(g_Ah + ((size_t)mt * 128 + m) * 32 + q * 8);
        *(uint4*)(&A_s[m * LDA + q * 8]) = v;
    }

    // --- B tile: g_Bh[b][c][nt*64+f] -> B_s[r(f)][kpos(c)], u32 (f-pair) loads.
    // Row permutation r(f): within each 16-f group, f = G+4*t4+rem maps to
    // r = G + (rem>=2 ? 8 : 0) + 2*t4 + (rem&1)  -> epilogue f's coalesce x4.
    {
        int c = t >> 3, fpb = t & 7;
        int pos = (c >> 4) * 16 + kpos(c & 15);
        const u32* src = (const u32*)(g_Bh + (size_t)b * (C_DIM * F_DIM) + c * F_DIM + nt * 64);
        #pragma unroll
        for (int j = 0; j < 4; j++) {
            int fp = fpb + 8 * j;
            u32 v = src[fp];
            int f = 2 * fp;
            int r = (f & ~15) + ((f & 2) << 2) + (((f >> 2) & 3) << 1);
            B_s[r * LDB + pos]       = (u16)(v & 0xffffu);
            B_s[(r + 1) * LDB + pos] = (u16)(v >> 16);
        }
    }
    if (t < 64) bo_s[t] = bo[nt * 64 + t];
    __syncthreads();

    float acc[2][4][4];
    #pragma unroll
    for (int mi = 0; mi < 2; mi++)
        #pragma unroll
        for (int ni = 0; ni < 4; ni++)
            #pragma unroll
            for (int q = 0; q < 4; q++) acc[mi][ni][q] = 0.f;

    #pragma unroll
    for (int kb = 0; kb < 2; kb++) {
        int col = kb * 16 + tig * 4;

        u32 af[2][4], bfr[4][2];
        #pragma unroll
        for (int mi = 0; mi < 2; mi++) {
            int row = m0 + mi * 16 + g;
            uint2 v0 = *(const uint2*)&A_s[row * LDA + col];
            uint2 v1 = *(const uint2*)&A_s[(row + 8) * LDA + col];
            af[mi][0] = v0.x; af[mi][2] = v0.y;
            af[mi][1] = v1.x; af[mi][3] = v1.y;
        }
        #pragma unroll
        for (int ni = 0; ni < 4; ni++) {
            uint2 v = *(const uint2*)&B_s[(n0 + ni * 8 + g) * LDB + col];
            bfr[ni][0] = v.x; bfr[ni][1] = v.y;
        }
        #pragma unroll
        for (int mi = 0; mi < 2; mi++)
            #pragma unroll
            for (int ni = 0; ni < 4; ni++)
                mma_f16(acc[mi][ni], af[mi], bfr[ni]);
    }

    // --- epilogue: STG.128, thread (g,tig) owns f = (wn*2+p)*16 + 4*tig ---
    #pragma unroll
    for (int mi = 0; mi < 2; mi++) {
        size_t a_row = (size_t)mt * 128 + m0 + mi * 16 + g;
        float* prow  = out + a_row * ((size_t)A_NODES * F_DIM) + (size_t)b * F_DIM + nt * 64;
        float* prow8 = prow + 8 * ((size_t)A_NODES * F_DIM);
        #pragma unroll
        for (int p = 0; p < 2; p++) {
            int ni0 = 2 * p, ni1 = 2 * p + 1;
            int fl = (wn * 2 + p) * 16 + tig * 4;
            float4 bv = *(const float4*)&bo_s[fl];
            float4 w0, w1;
            w0.x = acc[mi][ni0][0] + bv.x; w0.y = acc[mi][ni0][1] + bv.y;
            w0.z = acc[mi][ni1][0] + bv.z; w0.w = acc[mi][ni1][1] + bv.w;
            w1.x = acc[mi][ni0][2] + bv.x; w1.y = acc[mi][ni0][3] + bv.y;
            w1.z = acc[mi][ni1][2] + bv.z; w1.w = acc[mi][ni1][3] + bv.w;
            *(float4*)(prow + fl)  = w0;
            *(float4*)(prow8 + fl) = w1;
        }
    }
}

// ---------------- launch ------------------------------------------------------
extern "C" void kernel_launch(void* const* d_in, const int* in_sizes, int n_in,
                              void* d_out, int out_size) {
    const float* nv   = (const float*)d_in[0];
    const float* mask = (const float*)d_in[1];
    const float* lns  = (const float*)d_in[2];
    const float* lnb  = (const float*)d_in[3];
    const float* Wl   = (const float*)d_in[4];
    const float* bl   = (const float*)d_in[5];
    const float* Wr   = (const float*)d_in[6];
    const float* br   = (const float*)d_in[7];
    const float* Wo   = (const float*)d_in[8];
    const float* bo   = (const float*)d_in[9];
    float* out = (float*)d_out;

    k_lnproj<<<A_NODES, 256>>>(nv, mask, lns, lnb, Wl, bl, Wr, br);
    k_makeT<<<dim3(32, 8), 256>>>(Wo);
    k_gemm<<<dim3(256, 2, 4), 256>>>(bo, out);
}